// round 11
// baseline (speedup 1.0000x reference)
#include <cuda_runtime.h>
#include <cstdint>

// Problem constants
#define BATCH 16
#define CH    256
#define HH    64
#define WW    64
#define TROWS 66                 // 64 data rows + top/bottom zero rows
#define ROWF  68                 // smem row stride (floats); data at cols 0..63
#define NBUF  2
#define BUFF  (TROWS * ROWF)     // 4488 floats per buffer
#define BUFB  (BUFF * 4)         // 17952 bytes per buffer

// Split schedule: co0->32, co1->16, co2->8, co3->4, co4->2 chunks, rest->1.
#define NSPLIT 62
#define NENT   (NSPLIT + 251)    // 313 schedule entries
#define NBLK   (NENT * BATCH)    // 5008 blocks, b fastest-varying

// ---------------------------------------------------------------------------
// Scratch (device globals — no runtime allocation allowed)
// ---------------------------------------------------------------------------
__device__ float g_scale[CH * CH];
__device__ int   g_cin  [CH * CH];
__device__ float g_w    [CH * CH * 24];   // per slot: 9 duplicated pairs (w,w) + pad
__device__ int   g_count[CH];
__device__ float g_part [NSPLIT * BATCH * HH * WW];   // ~16.25 MB partials

// ---------------------------------------------------------------------------
// cp.async + packed f32x2 helpers
// ---------------------------------------------------------------------------
__device__ __forceinline__ void cp_async16(uint32_t saddr, const float* gptr, int src_size) {
    asm volatile("cp.async.ca.shared.global [%0], [%1], 16, %2;\n"
                 :: "r"(saddr), "l"(gptr), "r"(src_size));
}
__device__ __forceinline__ void cp_commit() {
    asm volatile("cp.async.commit_group;\n" ::);
}
template <int N> __device__ __forceinline__ void cp_wait() {
    asm volatile("cp.async.wait_group %0;\n" :: "n"(N));
}
__device__ __forceinline__ unsigned long long pk2(float lo, float hi) {
    unsigned long long r;
    asm("mov.b64 %0, {%1, %2};" : "=l"(r) : "f"(lo), "f"(hi));
    return r;
}
__device__ __forceinline__ void fma2(unsigned long long& d,
                                     unsigned long long a, unsigned long long b) {
    asm("fma.rn.f32x2 %0, %1, %2, %0;" : "+l"(d) : "l"(a), "l"(b));
}
__device__ __forceinline__ void upk2(float& lo, float& hi, unsigned long long v) {
    asm("mov.b64 {%0, %1}, %2;" : "=f"(lo), "=f"(hi) : "l"(v));
}

// ---------------------------------------------------------------------------
// K1a: parallel cumprod (Kogge-Stone, 8 steps). Block = cin, thread = cout.
// ---------------------------------------------------------------------------
__global__ void scan_kernel(const float* __restrict__ weight) {
    int cin = blockIdx.x;
    int co  = threadIdx.x;
    __shared__ float sh[CH];
    sh[co] = (co == 0) ? 1.0f : fmaxf(weight[co * CH + cin], 0.0f);
    __syncthreads();
    #pragma unroll
    for (int off = 1; off < CH; off <<= 1) {
        float t = (co >= off) ? sh[co - off] : 1.0f;
        __syncthreads();
        sh[co] *= t;
        __syncthreads();
    }
    g_scale[co * CH + cin] = sh[co];
}

// ---------------------------------------------------------------------------
// K1b: deterministic per-cout compaction; stores each scaled weight as a
// duplicated (w, w) 64-bit pair so the conv loop issues no packing movs.
// ---------------------------------------------------------------------------
__global__ void compact_kernel(const float* __restrict__ conv_w) {
    int co  = blockIdx.x;
    int cin = threadIdx.x;
    float sc = g_scale[co * CH + cin];
    bool active = (sc != 0.0f);
    unsigned mask = __ballot_sync(0xffffffffu, active);
    int lane = cin & 31, warp = cin >> 5;
    __shared__ int wcnt[8];
    if (lane == 0) wcnt[warp] = __popc(mask);
    __syncthreads();
    int base = 0;
    #pragma unroll
    for (int i = 0; i < 8; i++)
        if (i < warp) base += wcnt[i];
    if (active) {
        int slot = base + __popc(mask & ((1u << lane) - 1u));
        g_cin[co * CH + slot] = cin;
        const float* ws = conv_w + (size_t)(co * CH + cin) * 9;
        float*       wd = g_w    + (size_t)(co * CH + slot) * 24;
        #pragma unroll
        for (int k = 0; k < 9; k++) {
            float v = ws[k] * sc;
            wd[2 * k]     = v;
            wd[2 * k + 1] = v;
        }
        #pragma unroll
        for (int k = 18; k < 24; k++) wd[k] = 0.0f;
    }
    if (cin == 0) {
        int t = 0;
        #pragma unroll
        for (int i = 0; i < 8; i++) t += wcnt[i];
        g_count[co] = t;
    }
}

// ---------------------------------------------------------------------------
// K2: whole-plane 3x3 conv over a chunk of the compacted channel list.
// 1-D grid (b fastest) for even work-block placement, 256 threads, 4x4
// micro-tile per thread, 2-buffer cp.async ring, packed f32x2 accumulation
// (column pairs), one aligned LDS.128 + 2 shuffles per row.
// ---------------------------------------------------------------------------
__global__ __launch_bounds__(256, 4) void conv_kernel(const float* __restrict__ in,
                                                      const float* __restrict__ bias,
                                                      float* __restrict__ out) {
    int y   = blockIdx.x >> 4;       // schedule entry
    int b   = blockIdx.x & 15;       // batch (fastest -> spread across SMs)
    int tid = threadIdx.x;
    int cg  = tid & 15;
    int rg  = tid >> 4;

    // Static schedule entry -> (cout, nchunks, chunk, partial slot)
    int co, nck, ch, pslot;
    if      (y < 32) { co = 0;      nck = 32; ch = y;      pslot = y;  }
    else if (y < 48) { co = 1;      nck = 16; ch = y - 32; pslot = y;  }
    else if (y < 56) { co = 2;      nck = 8;  ch = y - 48; pslot = y;  }
    else if (y < 60) { co = 3;      nck = 4;  ch = y - 56; pslot = y;  }
    else if (y < 62) { co = 4;      nck = 2;  ch = y - 60; pslot = y;  }
    else             { co = y - 57; nck = 1;  ch = 0;      pslot = -1; }

    int cnt = g_count[co];
    int lo  = ch * cnt / nck;
    int n   = (ch + 1) * cnt / nck - lo;
    int cobase = co * CH;

    extern __shared__ __align__(16) float smem[];   // [NBUF][TROWS][ROWF]
    uint32_t smem_u32 = (uint32_t)__cvta_generic_to_shared(smem);

    unsigned long long accp[4][2] = {};   // 4 rows x (col-pair 01, col-pair 23)

    if (n > 0) {
        // 1056 16B copies per tile: i = 0..3 all threads; i = 4 for tid < 32.
        auto issue = [&](int s) {
            const float* plane = in + (((size_t)b * CH + g_cin[cobase + lo + s]) << 12);
            uint32_t bo = (uint32_t)(s & 1) * BUFB;
            #pragma unroll
            for (int i = 0; i < 5; i++) {
                int idx = tid + 256 * i;
                if (i < 4 || tid < 32) {
                    int r = idx >> 4, c4 = idx & 15;
                    int gy = r - 1;
                    int sz = (gy >= 0 && gy < HH) ? 16 : 0;
                    cp_async16(smem_u32 + bo + (uint32_t)((r * ROWF + 4 * c4) * 4),
                               plane + gy * WW + c4 * 4, sz);
                }
            }
            cp_commit();
        };

        issue(0);

        for (int s = 0; s < n; ++s) {
            cp_wait<0>();
            __syncthreads();              // slot s visible; other buffer free

            if (s + 1 < n) issue(s + 1);

            // 9 pre-duplicated (w,w) pairs, uniform across the block.
            const unsigned long long* wp =
                reinterpret_cast<const unsigned long long*>(g_w + (size_t)(cobase + lo + s) * 24);
            unsigned long long wq[9];
            #pragma unroll
            for (int k = 0; k < 9; k++) wq[k] = __ldg(wp + k);

            const float* tb = smem + (s & 1) * BUFF;
            #pragma unroll
            for (int r = 0; r < 6; r++) {
                float4 m = *reinterpret_cast<const float4*>(tb + (4 * rg + r) * ROWF + 4 * cg);
                float lft = __shfl_up_sync(0xffffffffu, m.w, 1);
                float rgt = __shfl_down_sync(0xffffffffu, m.x, 1);
                if (cg == 0)  lft = 0.0f;
                if (cg == 15) rgt = 0.0f;
                unsigned long long pA = pk2(lft, m.x);   // (v0,v1)
                unsigned long long pB = pk2(m.x, m.y);   // (v1,v2)
                unsigned long long pC = pk2(m.y, m.z);   // (v2,v3)
                unsigned long long pD = pk2(m.z, m.w);   // (v3,v4)
                unsigned long long pE = pk2(m.w, rgt);   // (v4,v5)
                #pragma unroll
                for (int dy = 0; dy < 3; dy++) {
                    int orow = r - dy;
                    if (orow >= 0 && orow < 4) {
                        fma2(accp[orow][0], wq[dy * 3 + 0], pA);
                        fma2(accp[orow][0], wq[dy * 3 + 1], pB);
                        fma2(accp[orow][0], wq[dy * 3 + 2], pC);
                        fma2(accp[orow][1], wq[dy * 3 + 0], pC);
                        fma2(accp[orow][1], wq[dy * 3 + 1], pD);
                        fma2(accp[orow][1], wq[dy * 3 + 2], pE);
                    }
                }
            }
        }
    }

    // Unpack accumulators.
    float acc[4][4];
    #pragma unroll
    for (int r = 0; r < 4; r++) {
        upk2(acc[r][0], acc[r][1], accp[r][0]);
        upk2(acc[r][2], acc[r][3], accp[r][1]);
    }

    if (pslot < 0) {
        float bv = __ldg(bias + co);
        float4* o4 = reinterpret_cast<float4*>(out) + (((size_t)b * CH + co) << 10);
        #pragma unroll
        for (int r = 0; r < 4; r++) {
            int py = 4 * rg + r;
            o4[(py << 4) + cg] =
                make_float4(acc[r][0] + bv, acc[r][1] + bv, acc[r][2] + bv, acc[r][3] + bv);
        }
    } else {
        // Unconditional partial write (replay-safe even when n == 0).
        float4* p4 = reinterpret_cast<float4*>(g_part) + ((size_t)pslot * BATCH + b) * 1024;
        #pragma unroll
        for (int r = 0; r < 4; r++) {
            int py = 4 * rg + r;
            p4[(py << 4) + cg] = make_float4(acc[r][0], acc[r][1], acc[r][2], acc[r][3]);
        }
    }
}

// ---------------------------------------------------------------------------
// K3: reduce partials for the 5 split couts, add bias.
// grid = 5*16*4 = 320 blocks, 256 threads, 1 float4/thread, unrolled guarded
// 32-deep k-loop (MLP up to 32).
// ---------------------------------------------------------------------------
__global__ __launch_bounds__(256) void reduce_kernel(const float* __restrict__ bias,
                                                     float* __restrict__ out) {
    const int nck_t[5]   = {32, 16, 8, 4, 2};
    const int pbase_t[5] = {0, 32, 48, 56, 60};
    int blk = blockIdx.x;
    int co  = blk >> 6;            // 0..4
    int rem = blk & 63;
    int b   = rem >> 2;            // 0..15
    int q   = rem & 3;             // px chunk
    int nck = nck_t[co], pbase = pbase_t[co];

    int v4 = q * 256 + threadIdx.x;          // 0..1023 float4 index
    float bv = __ldg(bias + co);
    float4 acc = make_float4(bv, bv, bv, bv);

    const float4* part4 = reinterpret_cast<const float4*>(g_part);
    size_t base = ((size_t)pbase * BATCH + b) * 1024 + v4;
    const size_t stride = (size_t)BATCH * 1024;

    #pragma unroll
    for (int k = 0; k < 32; ++k) {
        if (k < nck) {
            float4 p = part4[base + (size_t)k * stride];
            acc.x += p.x; acc.y += p.y; acc.z += p.z; acc.w += p.w;
        }
    }

    reinterpret_cast<float4*>(out)[(((size_t)b * CH + co) << 10) + v4] = acc;
}

// ---------------------------------------------------------------------------
// Entry point. Inputs (metadata order): input, conv_w, conv_b, weight.
// ---------------------------------------------------------------------------
extern "C" void kernel_launch(void* const* d_in, const int* in_sizes, int n_in,
                              void* d_out, int out_size) {
    (void)in_sizes; (void)n_in; (void)out_size;
    const float* input  = (const float*)d_in[0];
    const float* conv_w = (const float*)d_in[1];
    const float* conv_b = (const float*)d_in[2];
    const float* weight = (const float*)d_in[3];
    float* out = (float*)d_out;

    const int dyn_smem = NBUF * BUFB;   // 35904 bytes
    cudaFuncSetAttribute(conv_kernel, cudaFuncAttributeMaxDynamicSharedMemorySize, dyn_smem);

    scan_kernel<<<CH, CH>>>(weight);
    compact_kernel<<<CH, CH>>>(conv_w);
    conv_kernel<<<NBLK, 256, dyn_smem>>>(input, conv_b, out);
    reduce_kernel<<<5 * BATCH * 4, 256>>>(conv_b, out);
}